// round 3
// baseline (speedup 1.0000x reference)
#include <cuda_runtime.h>
#include <cstdint>
#include <cstddef>

// ---------------------------------------------------------------------------
// 2-layer LSTM, B=32, T=512, I=H=1024, fp32.
// out = [outputs (32*512*1024)] [h_n (2*32*1024)] [c_n (2*32*1024)]
//
// Persistent kernel, 128 CTAs x 256 threads, one CTA per SM (forced by ~196KB
// dynamic smem), global sense-reversing barrier between the 1024 layer-steps.
// Per phase each CTA computes 8 neurons x 4 gates x 32 batches (k = 2048 dot
// products): warp = 4 gate rows, lane = batch, MACs via packed fma.rn.f32x2,
// W streamed through smem (broadcast LDS), activations in a swizzled smem
// tile, c-state in registers for all 512 steps.
// ---------------------------------------------------------------------------

#define NCTA   128
#define NTHR   256
#define TSTEPS 512
#define HDIM   1024

// h ping-pong buffers: [layer][pp][b*1024+n]
__device__ float g_h[2 * 2 * 32 * HDIM];
__device__ unsigned g_bar_count;
__device__ volatile unsigned g_bar_gen;

union F2 { unsigned long long u; float2 f; };

__device__ __forceinline__ void ffma2(unsigned long long& acc,
                                      unsigned long long a,
                                      unsigned long long b) {
    asm volatile("fma.rn.f32x2 %0, %1, %2, %0;" : "+l"(acc) : "l"(a), "l"(b));
}

__device__ __forceinline__ void grid_bar() {
    __syncthreads();
    if (threadIdx.x == 0) {
        __threadfence();                       // release: h writes visible
        unsigned gen = g_bar_gen;
        if (atomicAdd(&g_bar_count, 1u) == NCTA - 1) {
            g_bar_count = 0;
            __threadfence();
            g_bar_gen = gen + 1;               // release all
        } else {
            while (g_bar_gen == gen) { __nanosleep(32); }
        }
        __threadfence();                       // acquire
    }
    __syncthreads();
}

extern "C" __global__ void __launch_bounds__(NTHR, 1)
lstm_persist(const float* __restrict__ x,
             const float* __restrict__ W0, const float* __restrict__ b0,
             const float* __restrict__ W1, const float* __restrict__ b1,
             float* __restrict__ out)
{
    extern __shared__ float smem[];
    float* comb = smem;                 // [32][1024] activations (swizzled)
    float* Ws   = smem + 32768;         // [32][512] weight chunk
    float* gs   = smem + 49152;         // [32][33] gate results

    const int tid  = threadIdx.x;
    const int cta  = blockIdx.x;
    const int w    = tid >> 5;          // GEMM: warp -> local rows 4w..4w+3
    const int lane = tid & 31;          // GEMM: lane -> batch
    const int j    = tid & 7;           // pointwise: neuron within CTA
    const int bb   = tid >> 3;          // pointwise: batch
    const int ng   = cta * 8 + j;       // global neuron index

    // zero the h state buffers (both ping-pong slots)
    {
        int base = cta * 1024 + tid;
        #pragma unroll
        for (int k = 0; k < 4; k++) g_h[base + k * 256] = 0.f;
    }

    // per-thread biases: gate order f,i,g,o -> rows g*1024 + ng
    float br[2][4];
    #pragma unroll
    for (int g = 0; g < 4; ++g) {
        br[0][g] = b0[g * HDIM + ng];
        br[1][g] = b1[g * HDIM + ng];
    }
    float cst[2] = {0.f, 0.f};          // cell state, registers across all t

    grid_bar();                          // h buffers zeroed everywhere

    for (int t = 0; t < TSTEPS; ++t) {
        const int pp = t & 1;
        #pragma unroll 1
        for (int l = 0; l < 2; ++l) {
            const float* Wm = l ? W1 : W0;
            unsigned long long acc0 = 0, acc1 = 0, acc2 = 0, acc3 = 0;

            #pragma unroll 1
            for (int half = 0; half < 2; ++half) {
                // ---- stage comb[32][1024] (swizzled float4 layout) ----
                if (l == 0 && half == 0) {
                    // x_t : x[b][t][k]
                    const float4* src = (const float4*)x;
                    #pragma unroll
                    for (int i = 0; i < 32; i++) {
                        int flat = i * 256 + tid;
                        int b = flat >> 8, kq = flat & 255;
                        float4 v = __ldg(&src[(size_t)b * 131072 + (size_t)t * 256 + kq]);
                        *(float4*)&comb[(b * 256 + (kq ^ (b & 7))) << 2] = v;
                    }
                } else {
                    // half0 (l==1): layer0 output this step; half1: own h_prev
                    int lsrc = (half == 0) ? 0 : l;
                    int psrc = (half == 0) ? pp : (1 - pp);
                    const float4* src = (const float4*)&g_h[(lsrc * 2 + psrc) * 32768];
                    #pragma unroll
                    for (int i = 0; i < 32; i++) {
                        int flat = i * 256 + tid;
                        int b = flat >> 8, kq = flat & 255;
                        float4 v = __ldcg(&src[flat]);   // L2, never stale L1
                        *(float4*)&comb[(b * 256 + (kq ^ (b & 7))) << 2] = v;
                    }
                }
                __syncthreads();

                #pragma unroll 1
                for (int chunk = 0; chunk < 2; ++chunk) {
                    const int kbase = half * 1024 + chunk * 512;
                    // ---- stage Ws[32][512]: warp stages its 4 rows ----
                    #pragma unroll
                    for (int rr = 0; rr < 4; ++rr) {
                        int r    = 4 * w + rr;                       // local row
                        int grow = (r >> 3) * HDIM + cta * 8 + (r & 7); // W row
                        const float4* wsrc =
                            (const float4*)(Wm + (size_t)grow * 2048 + kbase);
                        float4* wdst = (float4*)(Ws + r * 512);
                        #pragma unroll
                        for (int i2 = 0; i2 < 4; i2++)
                            wdst[lane + 32 * i2] = __ldg(&wsrc[lane + 32 * i2]);
                    }
                    __syncthreads();

                    const float* wr0 = Ws + (4 * w + 0) * 512;
                    const float* wr1 = Ws + (4 * w + 1) * 512;
                    const float* wr2 = Ws + (4 * w + 2) * 512;
                    const float* wr3 = Ws + (4 * w + 3) * 512;
                    #pragma unroll 4
                    for (int kq = 0; kq < 128; ++kq) {
                        int kt = chunk * 128 + kq;
                        ulonglong2 cv =
                            *(const ulonglong2*)&comb[(lane * 256 + (kt ^ (lane & 7))) << 2];
                        ulonglong2 w0v = *(const ulonglong2*)&wr0[kq << 2];
                        ulonglong2 w1v = *(const ulonglong2*)&wr1[kq << 2];
                        ulonglong2 w2v = *(const ulonglong2*)&wr2[kq << 2];
                        ulonglong2 w3v = *(const ulonglong2*)&wr3[kq << 2];
                        ffma2(acc0, w0v.x, cv.x);  ffma2(acc0, w0v.y, cv.y);
                        ffma2(acc1, w1v.x, cv.x);  ffma2(acc1, w1v.y, cv.y);
                        ffma2(acc2, w2v.x, cv.x);  ffma2(acc2, w2v.y, cv.y);
                        ffma2(acc3, w3v.x, cv.x);  ffma2(acc3, w3v.y, cv.y);
                    }
                    __syncthreads();
                }
            }

            // ---- fold f32x2 halves, publish gates to smem ----
            {
                F2 u;
                u.u = acc0; gs[(4 * w + 0) * 33 + lane] = u.f.x + u.f.y;
                u.u = acc1; gs[(4 * w + 1) * 33 + lane] = u.f.x + u.f.y;
                u.u = acc2; gs[(4 * w + 2) * 33 + lane] = u.f.x + u.f.y;
                u.u = acc3; gs[(4 * w + 3) * 33 + lane] = u.f.x + u.f.y;
            }
            __syncthreads();

            // ---- pointwise: thread owns (neuron j, batch bb) ----
            float fg = gs[(0  + j) * 33 + bb] + br[l][0];
            float ig = gs[(8  + j) * 33 + bb] + br[l][1];
            float gg = gs[(16 + j) * 33 + bb] + br[l][2];
            float og = gs[(24 + j) * 33 + bb] + br[l][3];
            fg = 1.f / (1.f + expf(-fg));
            ig = 1.f / (1.f + expf(-ig));
            og = 1.f / (1.f + expf(-og));
            float c = fg * cst[l] + ig * tanhf(gg);
            cst[l] = c;
            float h = og * tanhf(c);

            g_h[(l * 2 + pp) * 32768 + bb * HDIM + ng] = h;
            if (l == 1)
                out[(size_t)bb * 524288 + (size_t)t * 1024 + ng] = h;
            if (t == TSTEPS - 1) {
                out[16777216 + l * 32768 + bb * 1024 + ng] = h;   // h_n
                out[16842752 + l * 32768 + bb * 1024 + ng] = c;   // c_n
            }

            grid_bar();
        }
    }
}

extern "C" void kernel_launch(void* const* d_in, const int* in_sizes, int n_in,
                              void* d_out, int out_size)
{
    (void)in_sizes; (void)n_in; (void)out_size;
    const float* x  = (const float*)d_in[0];
    const float* W0 = (const float*)d_in[1];
    const float* b0 = (const float*)d_in[2];
    const float* W1 = (const float*)d_in[3];
    const float* b1 = (const float*)d_in[4];

    const int smem_bytes = (32768 + 16384 + 32 * 33) * 4;   // 200832
    cudaFuncSetAttribute(lstm_persist,
                         cudaFuncAttributeMaxDynamicSharedMemorySize, smem_bytes);
    lstm_persist<<<NCTA, NTHR, smem_bytes>>>(x, W0, b0, W1, b1, (float*)d_out);
}